// round 7
// baseline (speedup 1.0000x reference)
#include <cuda_runtime.h>
#include <cstdint>

// Dense 2D spatial transformer (bilinear warp, zero-padded border).
// R6: per-row tap pairs fetched as ONE aligned LDG.128 window + FSEL extract
// (plus 25%-predicated straddle scalar), halving gather instructions and
// cutting L1tex wavefronts. Keeps R5's batched-MLP two-phase structure.
//
// input1: [1,1,4096,4096] f32 image
// input2: [1,2,4096,4096] f32 flow (plane 0 = dH, plane 1 = dW)
// out:    [1,1,4096,4096] f32
//
// Reference semantics (padded coords in [0,4097], zero border):
//   H_up = flow_h + h + 1 ; W_up = flow_w + w + 1
//   hf = clip(floor(H_up),0,4097); hc = clip(hf+1,0,4097); same for w
//   dH = hc - H_up; dW = wc - W_up   (weights from CLIPPED coords)
//   out = v00*dW*dH + v10*dW*(1-dH) + v01*(1-dW)*dH + v11*(1-dW)*(1-dH)

#define H_DIM 4096
#define W_DIM 4096
#define HP_MAX 4097

__device__ __forceinline__ float fetch_padded(const float* __restrict__ img, int h, int w) {
    bool in = ((unsigned)(h - 1) < (unsigned)H_DIM) & ((unsigned)(w - 1) < (unsigned)W_DIM);
    int idx = ((h - 1) << 12) + (w - 1);
    return in ? __ldg(img + idx) : 0.0f;
}

__global__ void __launch_bounds__(256, 4)
dense_warp_kernel(const float* __restrict__ img,
                  const float* __restrict__ flowH,
                  const float* __restrict__ flowW,
                  float* __restrict__ out) {
    int t = blockIdx.x * blockDim.x + threadIdx.x;
    int base = t << 2;                       // 4 consecutive pixels, same row

    float4 fh = *reinterpret_cast<const float4*>(flowH + base);
    float4 fw = *reinterpret_cast<const float4*>(flowW + base);

    int h = base >> 12;
    int w = base & (W_DIM - 1);

    const float hp1 = (float)(h + 1);
    const float wp1 = (float)(w + 1);

    float fhv[4] = {fh.x, fh.y, fh.z, fh.w};
    float fwv[4] = {fw.x, fw.y, fw.z, fw.w};

    float v00[4], v01[4], v10[4], v11[4];
    float dH[4], dW[4];

    // ---- phase 1: indices + window gathers + extraction ----
    #pragma unroll
    for (int k = 0; k < 4; k++) {
        float Hu = fhv[k] + hp1;
        float Wu = fwv[k] + wp1 + (float)k;

        float fhf = floorf(Hu);
        float fwf = floorf(Wu);
        int hf = (int)fhf;
        int wf = (int)fwf;

        if (((unsigned)(hf - 1) <= 4094u) & ((unsigned)(wf - 1) <= 4094u)) {
            dH[k] = (fhf + 1.0f) - Hu;
            dW[k] = (fwf + 1.0f) - Wu;
            int idx = (hf << 12) + wf - (W_DIM + 1);   // (hf-1)*4096 + (wf-1)
            int a   = idx & ~3;                        // 16B-aligned window base
            int r   = idx & 3;

            const float4 qt = __ldg(reinterpret_cast<const float4*>(img + a));
            const float4 qb = __ldg(reinterpret_cast<const float4*>(img + a + W_DIM));

            float et = 0.0f, eb = 0.0f;
            if (r == 3) {                              // pair straddles 16B window
                et = __ldg(img + idx + 1);
                eb = __ldg(img + idx + W_DIM + 1);
            }

            v00[k] = (r == 0) ? qt.x : (r == 1) ? qt.y : (r == 2) ? qt.z : qt.w;
            v01[k] = (r == 0) ? qt.y : (r == 1) ? qt.z : (r == 2) ? qt.w : et;
            v10[k] = (r == 0) ? qb.x : (r == 1) ? qb.y : (r == 2) ? qb.z : qb.w;
            v11[k] = (r == 0) ? qb.y : (r == 1) ? qb.z : (r == 2) ? qb.w : eb;
        } else {
            int hc = hf + 1, wc = wf + 1;
            int hfc = min(max(hf, 0), HP_MAX);
            int hcc = min(max(hc, 0), HP_MAX);
            int wfc = min(max(wf, 0), HP_MAX);
            int wcc = min(max(wc, 0), HP_MAX);
            dH[k] = (float)hcc - Hu;
            dW[k] = (float)wcc - Wu;
            v00[k] = fetch_padded(img, hfc, wfc);
            v01[k] = fetch_padded(img, hfc, wcc);
            v10[k] = fetch_padded(img, hcc, wfc);
            v11[k] = fetch_padded(img, hcc, wcc);
        }
    }

    // ---- phase 2: pure-FMA combine ----
    float o[4];
    #pragma unroll
    for (int k = 0; k < 4; k++) {
        float eH = 1.0f - dH[k];
        float eW = 1.0f - dW[k];
        float a = fmaf(eW, v01[k], dW[k] * v00[k]);
        float b = fmaf(eW, v11[k], dW[k] * v10[k]);
        o[k] = fmaf(eH, b, dH[k] * a);
    }

    float4 ov = make_float4(o[0], o[1], o[2], o[3]);
    *reinterpret_cast<float4*>(out + base) = ov;
}

extern "C" void kernel_launch(void* const* d_in, const int* in_sizes, int n_in,
                              void* d_out, int out_size) {
    const float* img   = (const float*)d_in[0];
    const float* flowH = (const float*)d_in[1];
    const float* flowW = (const float*)d_in[1] + (size_t)H_DIM * W_DIM;
    float* out = (float*)d_out;

    const int n_pix = H_DIM * W_DIM;
    const int threads = 256;
    const int blocks = (n_pix / 4) / threads;   // 16384
    dense_warp_kernel<<<blocks, threads>>>(img, flowH, flowW, out);
}

// round 8
// speedup vs baseline: 1.6009x; 1.6009x over previous
#include <cuda_runtime.h>
#include <cstdint>

// Dense 2D spatial transformer (bilinear warp, zero-padded border).
// R7: R5 structure (batched-MLP two-phase, interior fast path) with each row's
// tap pair fetched via one 8B-aligned LDG.64 (+50%-predicated scalar for the
// odd-offset case). Aligned 8B requests stay within one 32B sector, so this
// halves gather instructions without the LDG.128 data-return blowup seen in R6.
//
// input1: [1,1,4096,4096] f32 image
// input2: [1,2,4096,4096] f32 flow (plane 0 = dH, plane 1 = dW)
// out:    [1,1,4096,4096] f32
//
// Reference semantics (padded coords in [0,4097], zero border):
//   H_up = flow_h + h + 1 ; W_up = flow_w + w + 1
//   hf = clip(floor(H_up),0,4097); hc = clip(hf+1,0,4097); same for w
//   dH = hc - H_up; dW = wc - W_up   (weights from CLIPPED coords)
//   out = v00*dW*dH + v10*dW*(1-dH) + v01*(1-dW)*dH + v11*(1-dW)*(1-dH)

#define H_DIM 4096
#define W_DIM 4096
#define HP_MAX 4097

__device__ __forceinline__ float fetch_padded(const float* __restrict__ img, int h, int w) {
    bool in = ((unsigned)(h - 1) < (unsigned)H_DIM) & ((unsigned)(w - 1) < (unsigned)W_DIM);
    int idx = ((h - 1) << 12) + (w - 1);
    return in ? __ldg(img + idx) : 0.0f;
}

__global__ void __launch_bounds__(256, 4)
dense_warp_kernel(const float* __restrict__ img,
                  const float* __restrict__ flowH,
                  const float* __restrict__ flowW,
                  float* __restrict__ out) {
    int t = blockIdx.x * blockDim.x + threadIdx.x;
    int base = t << 2;                       // 4 consecutive pixels, same row

    float4 fh = *reinterpret_cast<const float4*>(flowH + base);
    float4 fw = *reinterpret_cast<const float4*>(flowW + base);

    int h = base >> 12;
    int w = base & (W_DIM - 1);

    const float hp1 = (float)(h + 1);
    const float wp1 = (float)(w + 1);

    float fhv[4] = {fh.x, fh.y, fh.z, fh.w};
    float fwv[4] = {fw.x, fw.y, fw.z, fw.w};

    float v00[4], v01[4], v10[4], v11[4];
    float dH[4], dW[4];

    // ---- phase 1: indices + merged-pair gathers ----
    #pragma unroll
    for (int k = 0; k < 4; k++) {
        float Hu = fhv[k] + hp1;
        float Wu = fwv[k] + wp1 + (float)k;

        float fhf = floorf(Hu);
        float fwf = floorf(Wu);
        int hf = (int)fhf;
        int wf = (int)fwf;

        if (((unsigned)(hf - 1) <= 4094u) & ((unsigned)(wf - 1) <= 4094u)) {
            dH[k] = (fhf + 1.0f) - Hu;
            dW[k] = (fwf + 1.0f) - Wu;
            int idx = (hf << 12) + wf - (W_DIM + 1);   // (hf-1)*4096 + (wf-1)
            int a   = idx & ~1;                        // 8B-aligned pair base
            bool odd = (idx & 1);

            float2 qt = __ldg(reinterpret_cast<const float2*>(img + a));
            float2 qb = __ldg(reinterpret_cast<const float2*>(img + a + W_DIM));

            float et = 0.0f, eb = 0.0f;
            if (odd) {                                 // pair straddles 8B window
                et = __ldg(img + idx + 1);
                eb = __ldg(img + idx + W_DIM + 1);
            }

            v00[k] = odd ? qt.y : qt.x;
            v01[k] = odd ? et   : qt.y;
            v10[k] = odd ? qb.y : qb.x;
            v11[k] = odd ? eb   : qb.y;
        } else {
            int hc = hf + 1, wc = wf + 1;
            int hfc = min(max(hf, 0), HP_MAX);
            int hcc = min(max(hc, 0), HP_MAX);
            int wfc = min(max(wf, 0), HP_MAX);
            int wcc = min(max(wc, 0), HP_MAX);
            dH[k] = (float)hcc - Hu;
            dW[k] = (float)wcc - Wu;
            v00[k] = fetch_padded(img, hfc, wfc);
            v01[k] = fetch_padded(img, hfc, wcc);
            v10[k] = fetch_padded(img, hcc, wfc);
            v11[k] = fetch_padded(img, hcc, wcc);
        }
    }

    // ---- phase 2: pure-FMA combine ----
    float o[4];
    #pragma unroll
    for (int k = 0; k < 4; k++) {
        float eH = 1.0f - dH[k];
        float eW = 1.0f - dW[k];
        float a = fmaf(eW, v01[k], dW[k] * v00[k]);
        float b = fmaf(eW, v11[k], dW[k] * v10[k]);
        o[k] = fmaf(eH, b, dH[k] * a);
    }

    float4 ov = make_float4(o[0], o[1], o[2], o[3]);
    *reinterpret_cast<float4*>(out + base) = ov;
}

extern "C" void kernel_launch(void* const* d_in, const int* in_sizes, int n_in,
                              void* d_out, int out_size) {
    const float* img   = (const float*)d_in[0];
    const float* flowH = (const float*)d_in[1];
    const float* flowW = (const float*)d_in[1] + (size_t)H_DIM * W_DIM;
    float* out = (float*)d_out;

    const int n_pix = H_DIM * W_DIM;
    const int threads = 256;
    const int blocks = (n_pix / 4) / threads;   // 16384
    dense_warp_kernel<<<blocks, threads>>>(img, flowH, flowW, out);
}